// round 14
// baseline (speedup 1.0000x reference)
#include <cuda_runtime.h>
#include <cuda_fp16.h>
#include <cstdint>

// Problem constants
#define BATCH 4
#define SEQ   2048
#define DMODEL 1024
#define NHEADS 16
#define DHEAD 64
#define MTOT (BATCH*SEQ)          // 8192
#define BHTOT (BATCH*NHEADS)      // 64

// Scratch (device globals), all fp16
__device__ __half g_Q[MTOT * DMODEL];
__device__ __half g_K[MTOT * DMODEL];
__device__ __half g_V[MTOT * DMODEL];
__device__ __half g_AO[MTOT * DMODEL];
__device__ __half g_Xh[MTOT * DMODEL];
__device__ __half g_Wh[4][DMODEL * DMODEL];

// ---------------------------------------------------------------------------
// Helpers
// ---------------------------------------------------------------------------
__device__ __forceinline__ uint32_t smem_u32(const void* p) {
    uint32_t a;
    asm("{ .reg .u64 t; cvta.to.shared.u64 t, %1; cvt.u32.u64 %0, t; }" : "=r"(a) : "l"(p));
    return a;
}
__device__ __forceinline__ void cpasync16(uint32_t dst, const void* src) {
    asm volatile("cp.async.cg.shared.global [%0], [%1], 16;" :: "r"(dst), "l"(src));
}
#define CP_COMMIT() asm volatile("cp.async.commit_group;" ::: "memory")
#define CP_WAIT1()  asm volatile("cp.async.wait_group 1;" ::: "memory")
#define CP_WAIT0()  asm volatile("cp.async.wait_group 0;" ::: "memory")

__device__ __forceinline__ void mma_f16(float c[4], const uint32_t a[4], const uint32_t b[2]) {
    asm volatile("mma.sync.aligned.m16n8k16.row.col.f32.f16.f16.f32 "
        "{%0,%1,%2,%3}, {%4,%5,%6,%7}, {%8,%9}, {%0,%1,%2,%3};"
        : "+f"(c[0]), "+f"(c[1]), "+f"(c[2]), "+f"(c[3])
        : "r"(a[0]), "r"(a[1]), "r"(a[2]), "r"(a[3]), "r"(b[0]), "r"(b[1]));
}
__device__ __forceinline__ void ldsm_x4(uint32_t r[4], uint32_t addr) {
    asm volatile("ldmatrix.sync.aligned.m8n8.x4.shared.b16 {%0,%1,%2,%3}, [%4];"
        : "=r"(r[0]), "=r"(r[1]), "=r"(r[2]), "=r"(r[3]) : "r"(addr));
}
__device__ __forceinline__ void ldsm_x4t(uint32_t r[4], uint32_t addr) {
    asm volatile("ldmatrix.sync.aligned.m8n8.x4.trans.shared.b16 {%0,%1,%2,%3}, [%4];"
        : "=r"(r[0]), "=r"(r[1]), "=r"(r[2]), "=r"(r[3]) : "r"(addr));
}
__device__ __forceinline__ uint32_t pack_h2(float lo, float hi) {
    __half2 h = __floats2half2_rn(lo, hi);
    return *(uint32_t*)&h;
}

// ---------------------------------------------------------------------------
// Prep: convert x + weights fp32 -> fp16 (rn) once.
// ---------------------------------------------------------------------------
#define XN4 ((int)(MTOT * DMODEL / 4))
#define WN4 ((int)(DMODEL * DMODEL / 4))
#define PREP_TOT (XN4 + 4 * WN4)

__global__ void __launch_bounds__(256) prep_kernel(const float* __restrict__ x,
                                                   const float* __restrict__ wq,
                                                   const float* __restrict__ wk,
                                                   const float* __restrict__ wv,
                                                   const float* __restrict__ wo)
{
    const int i = blockIdx.x * 256 + threadIdx.x;
    if (i >= PREP_TOT) return;
    const float4* src;
    __half* dst;
    int off;
    if (i < XN4) {
        src = (const float4*)x; dst = g_Xh; off = i;
    } else {
        const int j = i - XN4;
        const int w = j / WN4;
        off = j - w * WN4;
        src = (const float4*)((w == 0) ? wq : (w == 1) ? wk : (w == 2) ? wv : wo);
        dst = g_Wh[w];
    }
    float4 v = src[off];
    uint2 pk;
    pk.x = pack_h2(v.x, v.y);
    pk.y = pack_h2(v.z, v.w);
    *(uint2*)(dst + (size_t)off * 4) = pk;
}

// ---------------------------------------------------------------------------
// fp16 mma.sync GEMM (m16n8k16): block 128x256, warp tile 64x64 (2m x 4n),
// 3-stage cp.async (48 KB/stage = 144 KB), one barrier per k-tile.
// C[m,n] = sum_k A[m,k] * W[n,k]; A,W fp16; accum fp32.
// ---------------------------------------------------------------------------
#define G_BM 128
#define G_BN 256
#define G_BK 64
#define G_NT (DMODEL / G_BK)       // 16
#define A_TILE_B (G_BM * 128)      // 16 KB
#define B_TILE_B (G_BN * 128)      // 32 KB
#define STAGE_B (A_TILE_B + B_TILE_B)   // 48 KB
#define G_STAGES 3
#define GEMM_SMEM (G_STAGES * STAGE_B)  // 144 KB

template<int OUT_HALF>
__device__ __forceinline__ void gemm_core(const __half* __restrict__ A,
                                          const __half* __restrict__ W,
                                          void* __restrict__ Cv,
                                          float scale)
{
    extern __shared__ __align__(16) char smc[];
    const uint32_t smb = smem_u32(smc);
    const int tid = threadIdx.x;
    const int wid = tid >> 5;
    const int lane = tid & 31;
    const int gro = lane >> 2;
    const int tig = lane & 3;
    const int wm = wid >> 2;       // 0..1
    const int wn = wid & 3;        // 0..3
    const int m0 = blockIdx.y * G_BM;
    const int n0 = blockIdx.x * G_BN;

    const int la_row16 = lane & 15;
    const int la_hb = lane >> 4;
    const int lb_rsub = ((lane >> 4) << 3) + (lane & 7);
    const int lb_hb = (lane >> 3) & 1;

    float acc[4][8][4];
#pragma unroll
    for (int mi = 0; mi < 4; mi++)
#pragma unroll
        for (int ni = 0; ni < 8; ni++)
#pragma unroll
            for (int q = 0; q < 4; q++) acc[mi][ni][q] = 0.f;

    auto load_tile = [&](int kt, int stage) {
        const uint32_t abase = smb + stage * STAGE_B;
        const uint32_t bbase = abase + A_TILE_B;
        // A: 1024 16B chunks
#pragma unroll
        for (int i = 0; i < 4; i++) {
            const int idx = i * 256 + tid;
            const int row = idx >> 3;
            const int c8 = idx & 7;
            const uint32_t doff = (uint32_t)row * 128 + ((c8 ^ (row & 7)) << 4);
            cpasync16(abase + doff, A + (size_t)(m0 + row) * DMODEL + kt * G_BK + c8 * 8);
        }
        // B: 2048 16B chunks
#pragma unroll
        for (int i = 0; i < 8; i++) {
            const int idx = i * 256 + tid;
            const int row = idx >> 3;
            const int c8 = idx & 7;
            const uint32_t doff = (uint32_t)row * 128 + ((c8 ^ (row & 7)) << 4);
            cpasync16(bbase + doff, W + (size_t)(n0 + row) * DMODEL + kt * G_BK + c8 * 8);
        }
        CP_COMMIT();
    };

    load_tile(0, 0);
    load_tile(1, 1);

    for (int kt = 0; kt < G_NT; kt++) {
        CP_WAIT1();              // tile kt resident
        __syncthreads();         // all warps done reading stage (kt+2)%3
        if (kt + 2 < G_NT) load_tile(kt + 2, (kt + 2) % G_STAGES);
        else               CP_COMMIT();

        const uint32_t abyte = smb + (uint32_t)((kt % G_STAGES) * STAGE_B);
        const uint32_t bbyte = abyte + A_TILE_B;

#pragma unroll
        for (int ks = 0; ks < 4; ks++) {
            uint32_t af[4][4], bf[8][2];
#pragma unroll
            for (int mi = 0; mi < 4; mi++) {
                const int row = wm * 64 + mi * 16 + la_row16;
                const uint32_t c = 2 * ks + la_hb;
                ldsm_x4(af[mi], abyte + (uint32_t)row * 128 + ((c ^ (row & 7)) << 4));
            }
#pragma unroll
            for (int np = 0; np < 4; np++) {
                const int row = wn * 64 + np * 16 + lb_rsub;
                const uint32_t c = 2 * ks + lb_hb;
                uint32_t t4[4];
                ldsm_x4(t4, bbyte + (uint32_t)row * 128 + ((c ^ (row & 7)) << 4));
                bf[2 * np][0] = t4[0]; bf[2 * np][1] = t4[1];
                bf[2 * np + 1][0] = t4[2]; bf[2 * np + 1][1] = t4[3];
            }
#pragma unroll
            for (int mi = 0; mi < 4; mi++)
#pragma unroll
                for (int ni = 0; ni < 8; ni++)
                    mma_f16(acc[mi][ni], af[mi], bf[ni]);
        }
    }

#pragma unroll
    for (int mi = 0; mi < 4; mi++) {
        const int r0 = m0 + wm * 64 + mi * 16 + gro;
#pragma unroll
        for (int ni = 0; ni < 8; ni++) {
            const int cc = n0 + wn * 64 + ni * 8 + tig * 2;
            if (OUT_HALF) {
                __half* Ch = (__half*)Cv;
                uint32_t p0 = pack_h2(acc[mi][ni][0] * scale, acc[mi][ni][1] * scale);
                uint32_t p1 = pack_h2(acc[mi][ni][2] * scale, acc[mi][ni][3] * scale);
                *(uint32_t*)&Ch[(size_t)r0 * DMODEL + cc] = p0;
                *(uint32_t*)&Ch[(size_t)(r0 + 8) * DMODEL + cc] = p1;
            } else {
                float* Cf = (float*)Cv;
                *(float2*)&Cf[(size_t)r0 * DMODEL + cc] = make_float2(acc[mi][ni][0], acc[mi][ni][1]);
                *(float2*)&Cf[(size_t)(r0 + 8) * DMODEL + cc] = make_float2(acc[mi][ni][2], acc[mi][ni][3]);
            }
        }
    }
}

__global__ void __launch_bounds__(256) qkv_kernel()
{
    const __half* W = g_Wh[blockIdx.z];
    __half* C = (blockIdx.z == 0) ? g_Q : (blockIdx.z == 1) ? g_K : g_V;
    const float scale = (blockIdx.z == 0) ? 0.125f : 1.0f;   // fold 1/sqrt(64) into Q
    gemm_core<1>(g_Xh, W, C, scale);
}

__global__ void __launch_bounds__(256) proj_kernel(float* __restrict__ out)
{
    gemm_core<0>(g_AO, g_Wh[3], out, 1.0f);
}

// ---------------------------------------------------------------------------
// Flash attention, fp16 mma.sync m16n8k16 + ldmatrix(.trans), causal.
// 128 q-rows x 64 k-cols per step, 256 threads (8 warps x 16 rows).
// Smem: [Q->P: 16K][K: 2x8K][V: 2x8K] = 48 KB, swizzled rows.  (unchanged R13)
// ---------------------------------------------------------------------------
#define QP_B 16384
#define KV_B 8192
#define ATT_SMEM (QP_B + 4 * KV_B)     // 49152

__global__ void __launch_bounds__(256, 2) attn_kernel()
{
    extern __shared__ __align__(16) char smc[];
    const uint32_t smb_qp = smem_u32(smc);
    const uint32_t smb_k  = smb_qp + QP_B;
    const uint32_t smb_v  = smb_qp + QP_B + 2 * KV_B;
    __half* s_qp = (__half*)smc;

    const int tid = threadIdx.x;
    const int wid = tid >> 5;
    const int lane = tid & 31;
    const int gro = lane >> 2;
    const int tig = lane & 3;
    const int rq = wid * 16;

    const int la_row16 = lane & 15;
    const int la_hb = lane >> 4;
    const int lb_rsub = ((lane >> 4) << 3) + (lane & 7);
    const int lb_hb = (lane >> 3) & 1;
    const int lv_row = (((lane >> 3) & 1) << 3) + (lane & 7);
    const int lv_hb = lane >> 4;

    const int qt = gridDim.x - 1 - blockIdx.x;   // heavy blocks first
    const int bh = blockIdx.y;
    const int q0 = qt * 128;
    const int b = bh >> 4;
    const int h = bh & 15;

    const __half* Qb = g_Q + (size_t)(b * SEQ) * DMODEL + h * DHEAD;
    const __half* Kb = g_K + (size_t)(b * SEQ) * DMODEL + h * DHEAD;
    const __half* Vb = g_V + (size_t)(b * SEQ) * DMODEL + h * DHEAD;

    // ---- async-load Q tile (128 rows x 64 fp16 = 128B rows, swizzled) ----
    {
#pragma unroll
        for (int i = 0; i < 4; i++) {
            const int idx = i * 256 + tid;
            const int r = idx >> 3;
            const int c8 = idx & 7;
            const uint32_t doff = (uint32_t)r * 128 + ((c8 ^ (r & 7)) << 4);
            cpasync16(smb_qp + doff, Qb + (size_t)(q0 + r) * DMODEL + c8 * 8);
        }
        CP_COMMIT();
    }

    auto load_kv = [&](int kt, int stage) {
        const int k0 = kt * 64;
        const __half* Kp = Kb + (size_t)k0 * DMODEL;
        const __half* Vp = Vb + (size_t)k0 * DMODEL;
        const uint32_t so = (uint32_t)stage * KV_B;
#pragma unroll
        for (int i = 0; i < 2; i++) {
            const int idx = i * 256 + tid;
            const int r = idx >> 3;
            const int c8 = idx & 7;
            const uint32_t doff = (uint32_t)r * 128 + ((c8 ^ (r & 7)) << 4);
            cpasync16(smb_k + so + doff, Kp + (size_t)r * DMODEL + c8 * 8);
            cpasync16(smb_v + so + doff, Vp + (size_t)r * DMODEL + c8 * 8);
        }
        CP_COMMIT();
    };

    load_kv(0, 0);
    CP_WAIT0();
    __syncthreads();

    // ---- preload Q fragments (4 k-steps of k16) ----
    uint32_t qf[4][4];
#pragma unroll
    for (int ks = 0; ks < 4; ks++) {
        const int row = rq + la_row16;
        const uint32_t c = 2 * ks + la_hb;
        ldsm_x4(qf[ks], smb_qp + (uint32_t)row * 128 + ((c ^ (row & 7)) << 4));
    }

    float o[8][4];
#pragma unroll
    for (int nt = 0; nt < 8; nt++)
#pragma unroll
        for (int q = 0; q < 4; q++) o[nt][q] = 0.f;
    float m0 = -1e30f, m1 = -1e30f, l0 = 0.f, l1 = 0.f;

    const int nkt = 2 * qt + 2;
    int buf = 0;

    for (int kt = 0; kt < nkt; kt++) {
        CP_WAIT0();
        __syncthreads();
        if (kt + 1 < nkt) load_kv(kt + 1, buf ^ 1);

        const uint32_t kbyte = smb_k + (uint32_t)buf * KV_B;
        const uint32_t vbyte = smb_v + (uint32_t)buf * KV_B;

        // ---- S = Q K^T ----
        float s[8][4];
#pragma unroll
        for (int nt = 0; nt < 8; nt++)
#pragma unroll
            for (int q = 0; q < 4; q++) s[nt][q] = 0.f;

#pragma unroll
        for (int ks = 0; ks < 4; ks++) {
            uint32_t bk[8][2];
#pragma unroll
            for (int np = 0; np < 4; np++) {
                const int row = np * 16 + lb_rsub;
                const uint32_t c = 2 * ks + lb_hb;
                uint32_t t4[4];
                ldsm_x4(t4, kbyte + (uint32_t)row * 128 + ((c ^ (row & 7)) << 4));
                bk[2 * np][0] = t4[0]; bk[2 * np][1] = t4[1];
                bk[2 * np + 1][0] = t4[2]; bk[2 * np + 1][1] = t4[3];
            }
#pragma unroll
            for (int nt = 0; nt < 8; nt++)
                mma_f16(s[nt], qf[ks], bk[nt]);
        }

        // ---- causal mask (only last two k-tiles touch diagonal) ----
        if (kt >= 2 * qt) {
            const int gq0 = q0 + rq + gro;
            const int gq1 = gq0 + 8;
#pragma unroll
            for (int nt = 0; nt < 8; nt++) {
                const int gk = kt * 64 + nt * 8 + tig * 2;
                if (gk > gq0)     s[nt][0] = -1e30f;
                if (gk + 1 > gq0) s[nt][1] = -1e30f;
                if (gk > gq1)     s[nt][2] = -1e30f;
                if (gk + 1 > gq1) s[nt][3] = -1e30f;
            }
        }

        // ---- online softmax ----
        float mx0 = -1e30f, mx1 = -1e30f;
#pragma unroll
        for (int nt = 0; nt < 8; nt++) {
            mx0 = fmaxf(mx0, fmaxf(s[nt][0], s[nt][1]));
            mx1 = fmaxf(mx1, fmaxf(s[nt][2], s[nt][3]));
        }
        mx0 = fmaxf(mx0, __shfl_xor_sync(0xffffffffu, mx0, 1));
        mx0 = fmaxf(mx0, __shfl_xor_sync(0xffffffffu, mx0, 2));
        mx1 = fmaxf(mx1, __shfl_xor_sync(0xffffffffu, mx1, 1));
        mx1 = fmaxf(mx1, __shfl_xor_sync(0xffffffffu, mx1, 2));

        const float nm0 = fmaxf(m0, mx0);
        const float nm1 = fmaxf(m1, mx1);
        const float a0 = __expf(m0 - nm0);
        const float a1 = __expf(m1 - nm1);
        m0 = nm0; m1 = nm1;

        float rs0 = 0.f, rs1 = 0.f;
#pragma unroll
        for (int nt = 0; nt < 8; nt++) {
            s[nt][0] = __expf(s[nt][0] - nm0); rs0 += s[nt][0];
            s[nt][1] = __expf(s[nt][1] - nm0); rs0 += s[nt][1];
            s[nt][2] = __expf(s[nt][2] - nm1); rs1 += s[nt][2];
            s[nt][3] = __expf(s[nt][3] - nm1); rs1 += s[nt][3];
        }
        rs0 += __shfl_xor_sync(0xffffffffu, rs0, 1);
        rs0 += __shfl_xor_sync(0xffffffffu, rs0, 2);
        rs1 += __shfl_xor_sync(0xffffffffu, rs1, 1);
        rs1 += __shfl_xor_sync(0xffffffffu, rs1, 2);
        l0 = l0 * a0 + rs0;
        l1 = l1 * a1 + rs1;

        // rescale O; stage fp16 P into swizzled smem (own warp rows only)
#pragma unroll
        for (int nt = 0; nt < 8; nt++) {
            o[nt][0] *= a0; o[nt][1] *= a0; o[nt][2] *= a1; o[nt][3] *= a1;
            const int r0w = rq + gro, r1w = rq + gro + 8;
            const uint32_t off0 = (uint32_t)r0w * 128 + ((nt ^ (r0w & 7)) << 4) + tig * 4;
            const uint32_t off1 = (uint32_t)r1w * 128 + ((nt ^ (r1w & 7)) << 4) + tig * 4;
            *(uint32_t*)((char*)s_qp + off0) = pack_h2(s[nt][0], s[nt][1]);
            *(uint32_t*)((char*)s_qp + off1) = pack_h2(s[nt][2], s[nt][3]);
        }
        __syncwarp();

        // ---- O += P V  (V via ldmatrix.trans) ----
#pragma unroll
        for (int ks = 0; ks < 4; ks++) {
            uint32_t ap[4];
            {
                const int row = rq + la_row16;
                const uint32_t c = 2 * ks + la_hb;
                ldsm_x4(ap, smb_qp + (uint32_t)row * 128 + ((c ^ (row & 7)) << 4));
            }
#pragma unroll
            for (int ntp = 0; ntp < 4; ntp++) {
                const int row = ks * 16 + lv_row;
                const uint32_t c = 2 * ntp + lv_hb;
                uint32_t t4[4];
                ldsm_x4t(t4, vbyte + (uint32_t)row * 128 + ((c ^ (row & 7)) << 4));
                uint32_t bv0[2] = { t4[0], t4[1] };
                uint32_t bv1[2] = { t4[2], t4[3] };
                mma_f16(o[2 * ntp], ap, bv0);
                mma_f16(o[2 * ntp + 1], ap, bv1);
            }
        }

        buf ^= 1;
    }

    // ---- finalize + write fp16 AO ----
    const float inv0 = 1.f / l0;
    const float inv1 = 1.f / l1;
    __half* ao0 = g_AO + (size_t)(b * SEQ + q0 + rq + gro) * DMODEL + h * DHEAD;
    __half* ao1 = g_AO + (size_t)(b * SEQ + q0 + rq + gro + 8) * DMODEL + h * DHEAD;
#pragma unroll
    for (int nt = 0; nt < 8; nt++) {
        const int cc = nt * 8 + tig * 2;
        *(uint32_t*)&ao0[cc] = pack_h2(o[nt][0] * inv0, o[nt][1] * inv0);
        *(uint32_t*)&ao1[cc] = pack_h2(o[nt][2] * inv1, o[nt][3] * inv1);
    }
}

// ---------------------------------------------------------------------------
extern "C" void kernel_launch(void* const* d_in, const int* in_sizes, int n_in,
                              void* d_out, int out_size)
{
    const float* x  = (const float*)d_in[0];
    const float* wq = (const float*)d_in[1];
    const float* wk = (const float*)d_in[2];
    const float* wv = (const float*)d_in[3];
    const float* wo = (const float*)d_in[4];
    float* out = (float*)d_out;

    cudaFuncSetAttribute(qkv_kernel,  cudaFuncAttributeMaxDynamicSharedMemorySize, GEMM_SMEM);
    cudaFuncSetAttribute(proj_kernel, cudaFuncAttributeMaxDynamicSharedMemorySize, GEMM_SMEM);
    cudaFuncSetAttribute(attn_kernel, cudaFuncAttributeMaxDynamicSharedMemorySize, ATT_SMEM);

    prep_kernel<<<(PREP_TOT + 255) / 256, 256>>>(x, wq, wk, wv, wo);
    qkv_kernel<<<dim3(DMODEL / G_BN, MTOT / G_BM, 3), 256, GEMM_SMEM>>>();
    attn_kernel<<<dim3(SEQ / 128, BHTOT), 256, ATT_SMEM>>>();
    proj_kernel<<<dim3(DMODEL / G_BN, MTOT / G_BM), 256, GEMM_SMEM>>>(out);
}

// round 15
// speedup vs baseline: 1.1149x; 1.1149x over previous
#include <cuda_runtime.h>
#include <cuda_fp16.h>
#include <cstdint>

// Problem constants
#define BATCH 4
#define SEQ   2048
#define DMODEL 1024
#define NHEADS 16
#define DHEAD 64
#define MTOT (BATCH*SEQ)          // 8192
#define BHTOT (BATCH*NHEADS)      // 64

// Scratch (device globals), all fp16
__device__ __half g_Q[MTOT * DMODEL];
__device__ __half g_K[MTOT * DMODEL];
__device__ __half g_V[MTOT * DMODEL];
__device__ __half g_AO[MTOT * DMODEL];
__device__ __half g_Xh[MTOT * DMODEL];
__device__ __half g_Wh[4][DMODEL * DMODEL];

// ---------------------------------------------------------------------------
// Helpers
// ---------------------------------------------------------------------------
__device__ __forceinline__ uint32_t smem_u32(const void* p) {
    uint32_t a;
    asm("{ .reg .u64 t; cvta.to.shared.u64 t, %1; cvt.u32.u64 %0, t; }" : "=r"(a) : "l"(p));
    return a;
}
__device__ __forceinline__ void cpasync16(uint32_t dst, const void* src) {
    asm volatile("cp.async.cg.shared.global [%0], [%1], 16;" :: "r"(dst), "l"(src));
}
#define CP_COMMIT() asm volatile("cp.async.commit_group;" ::: "memory")
#define CP_WAIT1()  asm volatile("cp.async.wait_group 1;" ::: "memory")
#define CP_WAIT0()  asm volatile("cp.async.wait_group 0;" ::: "memory")

__device__ __forceinline__ void mma_f16(float c[4], const uint32_t a[4], const uint32_t b[2]) {
    asm volatile("mma.sync.aligned.m16n8k16.row.col.f32.f16.f16.f32 "
        "{%0,%1,%2,%3}, {%4,%5,%6,%7}, {%8,%9}, {%0,%1,%2,%3};"
        : "+f"(c[0]), "+f"(c[1]), "+f"(c[2]), "+f"(c[3])
        : "r"(a[0]), "r"(a[1]), "r"(a[2]), "r"(a[3]), "r"(b[0]), "r"(b[1]));
}
__device__ __forceinline__ void ldsm_x4(uint32_t r[4], uint32_t addr) {
    asm volatile("ldmatrix.sync.aligned.m8n8.x4.shared.b16 {%0,%1,%2,%3}, [%4];"
        : "=r"(r[0]), "=r"(r[1]), "=r"(r[2]), "=r"(r[3]) : "r"(addr));
}
__device__ __forceinline__ void ldsm_x4t(uint32_t r[4], uint32_t addr) {
    asm volatile("ldmatrix.sync.aligned.m8n8.x4.trans.shared.b16 {%0,%1,%2,%3}, [%4];"
        : "=r"(r[0]), "=r"(r[1]), "=r"(r[2]), "=r"(r[3]) : "r"(addr));
}
__device__ __forceinline__ uint32_t pack_h2(float lo, float hi) {
    __half2 h = __floats2half2_rn(lo, hi);
    return *(uint32_t*)&h;
}

// ---------------------------------------------------------------------------
// Prep: convert x + weights fp32 -> fp16 (rn) once.
// ---------------------------------------------------------------------------
#define XN4 ((int)(MTOT * DMODEL / 4))
#define WN4 ((int)(DMODEL * DMODEL / 4))
#define PREP_TOT (XN4 + 4 * WN4)

__global__ void __launch_bounds__(256) prep_kernel(const float* __restrict__ x,
                                                   const float* __restrict__ wq,
                                                   const float* __restrict__ wk,
                                                   const float* __restrict__ wv,
                                                   const float* __restrict__ wo)
{
    const int i = blockIdx.x * 256 + threadIdx.x;
    if (i >= PREP_TOT) return;
    const float4* src;
    __half* dst;
    int off;
    if (i < XN4) {
        src = (const float4*)x; dst = g_Xh; off = i;
    } else {
        const int j = i - XN4;
        const int w = j / WN4;
        off = j - w * WN4;
        src = (const float4*)((w == 0) ? wq : (w == 1) ? wk : (w == 2) ? wv : wo);
        dst = g_Wh[w];
    }
    float4 v = src[off];
    uint2 pk;
    pk.x = pack_h2(v.x, v.y);
    pk.y = pack_h2(v.z, v.w);
    *(uint2*)(dst + (size_t)off * 4) = pk;
}

// ---------------------------------------------------------------------------
// fp16 mma.sync GEMM (m16n8k16), R13 config: block 128x128, warp 64x32,
// 3-stage cp.async (96 KB), 2 blocks/SM, one barrier per k-tile.
// ---------------------------------------------------------------------------
#define G_BM 128
#define G_BN 128
#define G_BK 64
#define G_NT (DMODEL / G_BK)       // 16
#define TILE_B (G_BM * 128)        // 16 KB per operand tile
#define STAGE_B (2 * TILE_B)       // 32 KB
#define G_STAGES 3
#define GEMM_SMEM (G_STAGES * STAGE_B)  // 96 KB

template<int OUT_HALF>
__device__ __forceinline__ void gemm_core(const __half* __restrict__ A,
                                          const __half* __restrict__ W,
                                          void* __restrict__ Cv,
                                          float scale)
{
    extern __shared__ __align__(16) char smc[];
    const uint32_t smb = smem_u32(smc);
    const int tid = threadIdx.x;
    const int wid = tid >> 5;
    const int lane = tid & 31;
    const int gro = lane >> 2;
    const int tig = lane & 3;
    const int wm = wid >> 2;
    const int wn = wid & 3;
    const int m0 = blockIdx.y * G_BM;
    const int n0 = blockIdx.x * G_BN;

    const int la_row16 = lane & 15;
    const int la_hb = lane >> 4;
    const int lb_rsub = ((lane >> 4) << 3) + (lane & 7);
    const int lb_hb = (lane >> 3) & 1;

    float acc[4][4][4];
#pragma unroll
    for (int mi = 0; mi < 4; mi++)
#pragma unroll
        for (int ni = 0; ni < 4; ni++)
#pragma unroll
            for (int q = 0; q < 4; q++) acc[mi][ni][q] = 0.f;

    auto load_tile = [&](int kt, int stage) {
        const uint32_t abase = smb + stage * STAGE_B;
        const uint32_t bbase = abase + TILE_B;
#pragma unroll
        for (int i = 0; i < 4; i++) {
            const int idx = i * 256 + tid;
            const int row = idx >> 3;
            const int c8 = idx & 7;
            const uint32_t doff = (uint32_t)row * 128 + ((c8 ^ (row & 7)) << 4);
            cpasync16(abase + doff, A + (size_t)(m0 + row) * DMODEL + kt * G_BK + c8 * 8);
            cpasync16(bbase + doff, W + (size_t)(n0 + row) * DMODEL + kt * G_BK + c8 * 8);
        }
        CP_COMMIT();
    };

    load_tile(0, 0);
    load_tile(1, 1);

    for (int kt = 0; kt < G_NT; kt++) {
        CP_WAIT1();
        __syncthreads();
        if (kt + 2 < G_NT) load_tile(kt + 2, (kt + 2) % G_STAGES);
        else               CP_COMMIT();

        const uint32_t abyte = smb + (uint32_t)((kt % G_STAGES) * STAGE_B);
        const uint32_t bbyte = abyte + TILE_B;

#pragma unroll
        for (int ks = 0; ks < 4; ks++) {
            uint32_t af[4][4], bf[4][2];
#pragma unroll
            for (int mi = 0; mi < 4; mi++) {
                const int row = wm * 64 + mi * 16 + la_row16;
                const uint32_t c = 2 * ks + la_hb;
                ldsm_x4(af[mi], abyte + (uint32_t)row * 128 + ((c ^ (row & 7)) << 4));
            }
#pragma unroll
            for (int np = 0; np < 2; np++) {
                const int row = wn * 32 + np * 16 + lb_rsub;
                const uint32_t c = 2 * ks + lb_hb;
                uint32_t t4[4];
                ldsm_x4(t4, bbyte + (uint32_t)row * 128 + ((c ^ (row & 7)) << 4));
                bf[2 * np][0] = t4[0]; bf[2 * np][1] = t4[1];
                bf[2 * np + 1][0] = t4[2]; bf[2 * np + 1][1] = t4[3];
            }
#pragma unroll
            for (int mi = 0; mi < 4; mi++)
#pragma unroll
                for (int ni = 0; ni < 4; ni++)
                    mma_f16(acc[mi][ni], af[mi], bf[ni]);
        }
    }

#pragma unroll
    for (int mi = 0; mi < 4; mi++) {
        const int r0 = m0 + wm * 64 + mi * 16 + gro;
#pragma unroll
        for (int ni = 0; ni < 4; ni++) {
            const int cc = n0 + wn * 32 + ni * 8 + tig * 2;
            if (OUT_HALF) {
                __half* Ch = (__half*)Cv;
                uint32_t p0 = pack_h2(acc[mi][ni][0] * scale, acc[mi][ni][1] * scale);
                uint32_t p1 = pack_h2(acc[mi][ni][2] * scale, acc[mi][ni][3] * scale);
                *(uint32_t*)&Ch[(size_t)r0 * DMODEL + cc] = p0;
                *(uint32_t*)&Ch[(size_t)(r0 + 8) * DMODEL + cc] = p1;
            } else {
                float* Cf = (float*)Cv;
                *(float2*)&Cf[(size_t)r0 * DMODEL + cc] = make_float2(acc[mi][ni][0], acc[mi][ni][1]);
                *(float2*)&Cf[(size_t)(r0 + 8) * DMODEL + cc] = make_float2(acc[mi][ni][2], acc[mi][ni][3]);
            }
        }
    }
}

__global__ void __launch_bounds__(256, 2) qkv_kernel()
{
    const __half* W = g_Wh[blockIdx.z];
    __half* C = (blockIdx.z == 0) ? g_Q : (blockIdx.z == 1) ? g_K : g_V;
    const float scale = (blockIdx.z == 0) ? 0.125f : 1.0f;   // fold 1/sqrt(64) into Q
    gemm_core<1>(g_Xh, W, C, scale);
}

__global__ void __launch_bounds__(256, 2) proj_kernel(float* __restrict__ out)
{
    gemm_core<0>(g_AO, g_Wh[3], out, 1.0f);
}

// ---------------------------------------------------------------------------
// Flash attention, fp16 mma.sync m16n8k16, causal.
// 128 q-rows x 64 k-cols per step, 256 threads (8 warps x 16 rows).
// P is forwarded S-Cfrag -> PV-Afrag entirely in registers (no smem staging):
//   ap[ks] = {pack(s[2ks][0..1]), pack(s[2ks][2..3]),
//             pack(s[2ks+1][0..1]), pack(s[2ks+1][2..3])}
// Smem: [Q: 16K][K: 2x8K][V: 2x8K] = 48 KB -> 2 blocks/SM.
// ---------------------------------------------------------------------------
#define QP_B 16384
#define KV_B 8192
#define ATT_SMEM (QP_B + 4 * KV_B)     // 49152

__global__ void __launch_bounds__(256, 2) attn_kernel()
{
    extern __shared__ __align__(16) char smc[];
    const uint32_t smb_qp = smem_u32(smc);
    const uint32_t smb_k  = smb_qp + QP_B;
    const uint32_t smb_v  = smb_qp + QP_B + 2 * KV_B;

    const int tid = threadIdx.x;
    const int wid = tid >> 5;
    const int lane = tid & 31;
    const int gro = lane >> 2;
    const int tig = lane & 3;
    const int rq = wid * 16;

    const int la_row16 = lane & 15;
    const int la_hb = lane >> 4;
    const int lb_rsub = ((lane >> 4) << 3) + (lane & 7);
    const int lb_hb = (lane >> 3) & 1;
    const int lv_row = (((lane >> 3) & 1) << 3) + (lane & 7);
    const int lv_hb = lane >> 4;

    const int qt = gridDim.x - 1 - blockIdx.x;   // heavy blocks first
    const int bh = blockIdx.y;
    const int q0 = qt * 128;
    const int b = bh >> 4;
    const int h = bh & 15;

    const __half* Qb = g_Q + (size_t)(b * SEQ) * DMODEL + h * DHEAD;
    const __half* Kb = g_K + (size_t)(b * SEQ) * DMODEL + h * DHEAD;
    const __half* Vb = g_V + (size_t)(b * SEQ) * DMODEL + h * DHEAD;

    // ---- async-load Q tile (128 rows x 64 fp16 = 128B rows, swizzled) ----
    {
#pragma unroll
        for (int i = 0; i < 4; i++) {
            const int idx = i * 256 + tid;
            const int r = idx >> 3;
            const int c8 = idx & 7;
            const uint32_t doff = (uint32_t)r * 128 + ((c8 ^ (r & 7)) << 4);
            cpasync16(smb_qp + doff, Qb + (size_t)(q0 + r) * DMODEL + c8 * 8);
        }
        CP_COMMIT();
    }

    auto load_kv = [&](int kt, int stage) {
        const int k0 = kt * 64;
        const __half* Kp = Kb + (size_t)k0 * DMODEL;
        const __half* Vp = Vb + (size_t)k0 * DMODEL;
        const uint32_t so = (uint32_t)stage * KV_B;
#pragma unroll
        for (int i = 0; i < 2; i++) {
            const int idx = i * 256 + tid;
            const int r = idx >> 3;
            const int c8 = idx & 7;
            const uint32_t doff = (uint32_t)r * 128 + ((c8 ^ (r & 7)) << 4);
            cpasync16(smb_k + so + doff, Kp + (size_t)r * DMODEL + c8 * 8);
            cpasync16(smb_v + so + doff, Vp + (size_t)r * DMODEL + c8 * 8);
        }
        CP_COMMIT();
    };

    load_kv(0, 0);
    CP_WAIT0();
    __syncthreads();

    // ---- preload Q fragments (4 k-steps of k16) ----
    uint32_t qf[4][4];
#pragma unroll
    for (int ks = 0; ks < 4; ks++) {
        const int row = rq + la_row16;
        const uint32_t c = 2 * ks + la_hb;
        ldsm_x4(qf[ks], smb_qp + (uint32_t)row * 128 + ((c ^ (row & 7)) << 4));
    }

    float o[8][4];
#pragma unroll
    for (int nt = 0; nt < 8; nt++)
#pragma unroll
        for (int q = 0; q < 4; q++) o[nt][q] = 0.f;
    float m0 = -1e30f, m1 = -1e30f, l0 = 0.f, l1 = 0.f;

    const int nkt = 2 * qt + 2;
    int buf = 0;

    for (int kt = 0; kt < nkt; kt++) {
        CP_WAIT0();
        __syncthreads();
        if (kt + 1 < nkt) load_kv(kt + 1, buf ^ 1);

        const uint32_t kbyte = smb_k + (uint32_t)buf * KV_B;
        const uint32_t vbyte = smb_v + (uint32_t)buf * KV_B;

        // ---- S = Q K^T ----
        float s[8][4];
#pragma unroll
        for (int nt = 0; nt < 8; nt++)
#pragma unroll
            for (int q = 0; q < 4; q++) s[nt][q] = 0.f;

#pragma unroll
        for (int ks = 0; ks < 4; ks++) {
            uint32_t bk[8][2];
#pragma unroll
            for (int np = 0; np < 4; np++) {
                const int row = np * 16 + lb_rsub;
                const uint32_t c = 2 * ks + lb_hb;
                uint32_t t4[4];
                ldsm_x4(t4, kbyte + (uint32_t)row * 128 + ((c ^ (row & 7)) << 4));
                bk[2 * np][0] = t4[0]; bk[2 * np][1] = t4[1];
                bk[2 * np + 1][0] = t4[2]; bk[2 * np + 1][1] = t4[3];
            }
#pragma unroll
            for (int nt = 0; nt < 8; nt++)
                mma_f16(s[nt], qf[ks], bk[nt]);
        }

        // ---- causal mask (only last two k-tiles touch diagonal) ----
        if (kt >= 2 * qt) {
            const int gq0 = q0 + rq + gro;
            const int gq1 = gq0 + 8;
#pragma unroll
            for (int nt = 0; nt < 8; nt++) {
                const int gk = kt * 64 + nt * 8 + tig * 2;
                if (gk > gq0)     s[nt][0] = -1e30f;
                if (gk + 1 > gq0) s[nt][1] = -1e30f;
                if (gk > gq1)     s[nt][2] = -1e30f;
                if (gk + 1 > gq1) s[nt][3] = -1e30f;
            }
        }

        // ---- online softmax ----
        float mx0 = -1e30f, mx1 = -1e30f;
#pragma unroll
        for (int nt = 0; nt < 8; nt++) {
            mx0 = fmaxf(mx0, fmaxf(s[nt][0], s[nt][1]));
            mx1 = fmaxf(mx1, fmaxf(s[nt][2], s[nt][3]));
        }
        mx0 = fmaxf(mx0, __shfl_xor_sync(0xffffffffu, mx0, 1));
        mx0 = fmaxf(mx0, __shfl_xor_sync(0xffffffffu, mx0, 2));
        mx1 = fmaxf(mx1, __shfl_xor_sync(0xffffffffu, mx1, 1));
        mx1 = fmaxf(mx1, __shfl_xor_sync(0xffffffffu, mx1, 2));

        const float nm0 = fmaxf(m0, mx0);
        const float nm1 = fmaxf(m1, mx1);
        const float a0 = __expf(m0 - nm0);
        const float a1 = __expf(m1 - nm1);
        m0 = nm0; m1 = nm1;

        float rs0 = 0.f, rs1 = 0.f;
#pragma unroll
        for (int nt = 0; nt < 8; nt++) {
            s[nt][0] = __expf(s[nt][0] - nm0); rs0 += s[nt][0];
            s[nt][1] = __expf(s[nt][1] - nm0); rs0 += s[nt][1];
            s[nt][2] = __expf(s[nt][2] - nm1); rs1 += s[nt][2];
            s[nt][3] = __expf(s[nt][3] - nm1); rs1 += s[nt][3];
        }
        rs0 += __shfl_xor_sync(0xffffffffu, rs0, 1);
        rs0 += __shfl_xor_sync(0xffffffffu, rs0, 2);
        rs1 += __shfl_xor_sync(0xffffffffu, rs1, 1);
        rs1 += __shfl_xor_sync(0xffffffffu, rs1, 2);
        l0 = l0 * a0 + rs0;
        l1 = l1 * a1 + rs1;

        // ---- pack P fragments directly (S C-frag == PV A-frag layout) ----
        uint32_t pf[4][4];
#pragma unroll
        for (int ks = 0; ks < 4; ks++) {
            pf[ks][0] = pack_h2(s[2 * ks][0],     s[2 * ks][1]);
            pf[ks][1] = pack_h2(s[2 * ks][2],     s[2 * ks][3]);
            pf[ks][2] = pack_h2(s[2 * ks + 1][0], s[2 * ks + 1][1]);
            pf[ks][3] = pack_h2(s[2 * ks + 1][2], s[2 * ks + 1][3]);
        }

        // rescale O
#pragma unroll
        for (int nt = 0; nt < 8; nt++) {
            o[nt][0] *= a0; o[nt][1] *= a0; o[nt][2] *= a1; o[nt][3] *= a1;
        }

        // ---- O += P V  (V via ldmatrix.trans) ----
#pragma unroll
        for (int ks = 0; ks < 4; ks++) {
#pragma unroll
            for (int ntp = 0; ntp < 4; ntp++) {
                const int row = ks * 16 + lv_row;
                const uint32_t c = 2 * ntp + lv_hb;
                uint32_t t4[4];
                ldsm_x4t(t4, vbyte + (uint32_t)row * 128 + ((c ^ (row & 7)) << 4));
                uint32_t bv0[2] = { t4[0], t4[1] };
                uint32_t bv1[2] = { t4[2], t4[3] };
                mma_f16(o[2 * ntp], pf[ks], bv0);
                mma_f16(o[2 * ntp + 1], pf[ks], bv1);
            }
        }

        buf ^= 1;
    }

    // ---- finalize + write fp16 AO ----
    const float inv0 = 1.f / l0;
    const float inv1 = 1.f / l1;
    __half* ao0 = g_AO + (size_t)(b * SEQ + q0 + rq + gro) * DMODEL + h * DHEAD;
    __half* ao1 = g_AO + (size_t)(b * SEQ + q0 + rq + gro + 8) * DMODEL + h * DHEAD;
#pragma unroll
    for (int nt = 0; nt < 8; nt++) {
        const int cc = nt * 8 + tig * 2;
        *(uint32_t*)&ao0[cc] = pack_h2(o[nt][0] * inv0, o[nt][1] * inv0);
        *(uint32_t*)&ao1[cc] = pack_h2(o[nt][2] * inv1, o[nt][3] * inv1);
    }
}

// ---------------------------------------------------------------------------
extern "C" void kernel_launch(void* const* d_in, const int* in_sizes, int n_in,
                              void* d_out, int out_size)
{
    const float* x  = (const float*)d_in[0];
    const float* wq = (const float*)d_in[1];
    const float* wk = (const float*)d_in[2];
    const float* wv = (const float*)d_in[3];
    const float* wo = (const float*)d_in[4];
    float* out = (float*)d_out;

    cudaFuncSetAttribute(qkv_kernel,  cudaFuncAttributeMaxDynamicSharedMemorySize, GEMM_SMEM);
    cudaFuncSetAttribute(proj_kernel, cudaFuncAttributeMaxDynamicSharedMemorySize, GEMM_SMEM);
    cudaFuncSetAttribute(attn_kernel, cudaFuncAttributeMaxDynamicSharedMemorySize, ATT_SMEM);

    prep_kernel<<<(PREP_TOT + 255) / 256, 256>>>(x, wq, wk, wv, wo);
    qkv_kernel<<<dim3(DMODEL / G_BN, MTOT / G_BM, 3), 256, GEMM_SMEM>>>();
    attn_kernel<<<dim3(SEQ / 128, BHTOT), 256, ATT_SMEM>>>();
    proj_kernel<<<dim3(DMODEL / G_BN, MTOT / G_BM), 256, GEMM_SMEM>>>(out);
}